// round 1
// baseline (speedup 1.0000x reference)
#include <cuda_runtime.h>
#include <cstdint>

// Problem constants (fixed shapes for this problem instance)
#define NB   8      // batch
#define NH   8      // heads
#define TT   128    // time steps
#define HH   32     // height
#define WW   64     // width
#define LL   2048   // h*w
#define CIN  16     // 2*NH conv input channels
#define COUT 32     // conv output channels
#define KS   5      // conv kernel size
#define BN_EPS 1e-5f

// ---------------------------------------------------------------------------
// Device scratch (allocation-free rule: __device__ globals)
// ---------------------------------------------------------------------------
__device__ float  g_acum[(size_t)NB * TT * CIN * LL];   // [(b*T+t)][ic][l]  exclusive cumsum
__device__ float  g_cov [(size_t)NB * NH * TT * LL];    // [b][n][t][l]  (== output layout)
__device__ int    g_mask[NB * LL];                      // canonical mask (1 = padded)
__device__ double g_sum[NH];
__device__ double g_ss [NH];
__device__ float  g_cnt;
__device__ float  g_scale[NH], g_shift[NH];

// ---------------------------------------------------------------------------
// Kernel 0: mask canonicalization + stat-accumulator reset (runs every launch)
// Detects whether the mask buffer is packed bool bytes, int32, or float32.
// ---------------------------------------------------------------------------
__global__ void prep_kernel(const void* __restrict__ maskraw)
{
    __shared__ int s_hasF, s_hasP, s_cnt;
    const int tid = threadIdx.x;
    if (tid == 0) { s_hasF = 0; s_hasP = 0; s_cnt = 0; }
    __syncthreads();

    const unsigned* u32 = (const unsigned*)maskraw;
    // Scan only the first 16KB (safe for 1-byte-per-elem bool buffers too).
    int hf = 0, hp = 0;
    for (int i = tid; i < (NB * LL) / 4; i += blockDim.x) {
        unsigned v = u32[i];
        if (v == 0x3F800000u) hf = 1;      // float32 1.0 present -> float mask
        else if (v > 1u)      hp = 1;      // packed bool bytes (e.g. 0x0101)
    }
    if (hf) atomicOr(&s_hasF, 1);
    if (hp) atomicOr(&s_hasP, 1);
    __syncthreads();

    const int isBool = (!s_hasF) && s_hasP;
    const unsigned char* b8 = (const unsigned char*)maskraw;

    int localUnmasked = 0;
    for (int i = tid; i < NB * LL; i += blockDim.x) {
        int m = isBool ? (b8[i] != 0) : (u32[i] != 0u);
        g_mask[i] = m;
        localUnmasked += (m == 0);
    }
    atomicAdd(&s_cnt, localUnmasked);
    __syncthreads();

    if (tid == 0) {
        float cnt = (float)s_cnt * (float)TT;  // nm.sum() over (b*t,1,h,w)
        g_cnt = (cnt < 1.0f) ? 1.0f : cnt;
    }
    if (tid < NH) { g_sum[tid] = 0.0; g_ss[tid] = 0.0; }
}

// ---------------------------------------------------------------------------
// Kernel 1: exclusive cumsum over t, fused channel-concat [prev(8) | curr(8)],
// written in per-image layout [(b*T+t)][ic][l] for the conv stage.
// One thread per (b, ic, l); coalesced over l at every t step.
// ---------------------------------------------------------------------------
__global__ void cumsum_kernel(const float* __restrict__ prev,
                              const float* __restrict__ curr)
{
    const int gid = blockIdx.x * blockDim.x + threadIdx.x;   // 8*16*2048 = 262144
    const int b   = gid >> 15;
    const int rem = gid & 32767;
    const int cc  = rem >> 11;
    const int l   = rem & (LL - 1);

    const float* src = (cc < NH)
        ? prev + ((size_t)(b * NH + cc)       ) * TT * LL + l
        : curr + ((size_t)(b * NH + (cc - NH))) * TT * LL + l;

    size_t dst = ((size_t)(b * TT) * CIN + cc) * LL + l;

    float run = 0.0f;
    #pragma unroll 4
    for (int t = 0; t < TT; t++) {
        g_acum[dst] = run;            // exclusive: value BEFORE adding a_t
        run += src[(size_t)t * LL];
        dst += (size_t)CIN * LL;
    }
}

// ---------------------------------------------------------------------------
// Kernel 2: the hot kernel. Per block = one (b,t) image:
//   5x5 conv (16->32) + bias + ReLU + mask-zero + 1x1 proj (32->8)
//   + masked BN partial sums + cov store in final output layout.
// ---------------------------------------------------------------------------
#define SIN_STRIDE 68                       // 64 + 2*2 halo
#define SIN_ROWS   36                       // 32 + 2*2 halo
#define SIN_PER_C  (SIN_ROWS * SIN_STRIDE)  // 2448
#define SIN_FLOATS (CIN * SIN_PER_C)        // 39168
#define SW_FLOATS  (COUT * CIN * KS * KS)   // 12800
#define SMEM_FLOATS (SIN_FLOATS + SW_FLOATS + 256 + 32 + 16)
#define SMEM_BYTES  (SMEM_FLOATS * 4)       // 209088

__global__ __launch_bounds__(512, 1)
void conv_kernel(const float* __restrict__ convw,
                 const float* __restrict__ convb,
                 const float* __restrict__ projw)
{
    extern __shared__ float sm[];
    float* s_in   = sm;                         // [ic][36][68], halo zero-padded
    float* s_w    = sm + SIN_FLOATS;            // [kidx(ic,ky,kx)][oc]  (oc contiguous)
    float* s_proj = s_w + SW_FLOATS;            // [oc][n]
    float* s_cb   = s_proj + 256;               // [oc]
    float* s_blk  = s_cb + 32;                  // [sum(8) | sumsq(8)]

    const int tid = threadIdx.x;
    const int img = blockIdx.x;                 // = b*T + t
    const int b   = img >> 7;
    const int t   = img & (TT - 1);

    if (tid < 16)  s_blk[tid] = 0.0f;
    if (tid < 32)  s_cb[tid]  = convb[tid];
    if (tid < 256) {                            // s_proj[oc*8+n] = projw[n*32+oc]
        const int oc = tid >> 3, n = tid & 7;
        s_proj[tid] = projw[n * COUT + oc];
    }
    // weights: s_w[kidx*32 + oc] = convw[oc*400 + kidx]
    for (int i = tid; i < SW_FLOATS; i += 512) {
        const int oc = i & 31, kidx = i >> 5;
        s_w[i] = convw[oc * (CIN * KS * KS) + kidx];
    }
    // haloed input tile
    for (int i = tid; i < SIN_FLOATS; i += 512) {
        const int ic  = i / SIN_PER_C;
        const int rem = i - ic * SIN_PER_C;
        const int R   = rem / SIN_STRIDE;
        const int C   = rem - R * SIN_STRIDE;
        const int rin = R - 2, cin = C - 2;
        float v = 0.0f;
        if ((unsigned)rin < (unsigned)HH && (unsigned)cin < (unsigned)WW)
            v = g_acum[((size_t)img * CIN + ic) * LL + rin * WW + cin];
        s_in[i] = v;
    }
    __syncthreads();

    const int warp = tid >> 5, lane = tid & 31;

    // 32 tasks: 16 row-pairs x 2 column halves; 16 warps x 2 iterations.
    for (int task = warp; task < 32; task += 16) {
        const int r0 = (task & 15) * 2;
        const int c  = ((task >> 4) << 5) + lane;

        float acc0[COUT], acc1[COUT];
        #pragma unroll
        for (int o = 0; o < COUT; o++) { acc0[o] = 0.0f; acc1[o] = 0.0f; }

        #pragma unroll 1
        for (int ic = 0; ic < CIN; ic++) {
            const float* sc_ = s_in + ic * SIN_PER_C;
            #pragma unroll 1
            for (int ky = 0; ky < KS; ky++) {
                const float* r0p = sc_ + (r0 + ky) * SIN_STRIDE + c;  // + kx below
                const float* r1p = r0p + SIN_STRIDE;
                const float4* wb = reinterpret_cast<const float4*>(s_w)
                                 + (ic * 25 + ky * 5) * 8;
                #pragma unroll
                for (int kx = 0; kx < KS; kx++) {
                    const float i0 = r0p[kx];        // consecutive addrs -> no conflicts
                    const float i1 = r1p[kx];
                    const float4* w4 = wb + kx * 8;  // broadcast reads
                    #pragma unroll
                    for (int u = 0; u < 8; u++) {
                        const float4 w = w4[u];
                        acc0[4*u+0] += w.x * i0;  acc0[4*u+1] += w.y * i0;
                        acc0[4*u+2] += w.z * i0;  acc0[4*u+3] += w.w * i0;
                        acc1[4*u+0] += w.x * i1;  acc1[4*u+1] += w.y * i1;
                        acc1[4*u+2] += w.z * i1;  acc1[4*u+3] += w.w * i1;
                    }
                }
            }
        }

        // Epilogue: bias + ReLU + mask + 1x1 proj + store + BN partials
        float psum[NH], pss[NH];
        #pragma unroll
        for (int n = 0; n < NH; n++) { psum[n] = 0.0f; pss[n] = 0.0f; }

        #pragma unroll
        for (int r = 0; r < 2; r++) {
            const int row = r0 + r;
            const int hw  = row * WW + c;
            const int m   = g_mask[b * LL + hw];
            float p[NH];
            #pragma unroll
            for (int n = 0; n < NH; n++) p[n] = 0.0f;
            if (!m) {
                #pragma unroll
                for (int oc = 0; oc < COUT; oc++) {
                    float v = (r ? acc1[oc] : acc0[oc]) + s_cb[oc];
                    v = v > 0.0f ? v : 0.0f;
                    #pragma unroll
                    for (int n = 0; n < NH; n++) p[n] += v * s_proj[oc * NH + n];
                }
            }
            #pragma unroll
            for (int n = 0; n < NH; n++) {
                g_cov[(((size_t)(b * NH + n)) * TT + t) * LL + hw] = p[n];
                if (!m) { psum[n] += p[n]; pss[n] += p[n] * p[n]; }
            }
        }

        // warp reduce -> block smem accumulators
        #pragma unroll
        for (int n = 0; n < NH; n++) {
            float s = psum[n], q = pss[n];
            #pragma unroll
            for (int off = 16; off > 0; off >>= 1) {
                s += __shfl_xor_sync(0xffffffffu, s, off);
                q += __shfl_xor_sync(0xffffffffu, q, off);
            }
            if (lane == 0) {
                atomicAdd(&s_blk[n],      s);
                atomicAdd(&s_blk[NH + n], q);
            }
        }
    }

    __syncthreads();
    if (tid < NH) {
        atomicAdd(&g_sum[tid], (double)s_blk[tid]);
        atomicAdd(&g_ss[tid],  (double)s_blk[NH + tid]);
    }
}

// ---------------------------------------------------------------------------
// Kernel 3: BN finalize (tiny)
// ---------------------------------------------------------------------------
__global__ void finalize_kernel(const float* __restrict__ gamma,
                                const float* __restrict__ beta)
{
    const int n = threadIdx.x;
    if (n < NH) {
        const double cnt  = (double)g_cnt;
        const double mean = g_sum[n] / cnt;
        double var  = g_ss[n] / cnt - mean * mean;
        if (var < 0.0) var = 0.0;
        const float inv = rsqrtf((float)var + BN_EPS);
        g_scale[n] = gamma[n] * inv;
        g_shift[n] = beta[n] - gamma[n] * inv * (float)mean;
    }
}

// ---------------------------------------------------------------------------
// Kernel 4: normalize + mask-zero, write to output (same layout as g_cov)
// ---------------------------------------------------------------------------
__global__ void bn_kernel(float* __restrict__ out)
{
    const size_t i4  = (size_t)blockIdx.x * blockDim.x + threadIdx.x;
    const size_t idx = i4 * 4;
    const int n  = (int)((idx >> 18) & 7);     // idx / (T*L) % NH
    const int b  = (int)(idx >> 21);           // idx / (NH*T*L)
    const int hw = (int)(idx & (LL - 1));

    const float4 v = *reinterpret_cast<const float4*>(&g_cov[idx]);
    const int4   m = *reinterpret_cast<const int4*>(&g_mask[b * LL + hw]);
    const float sc = g_scale[n], sh = g_shift[n];

    float4 o;
    o.x = m.x ? 0.0f : fmaf(v.x, sc, sh);
    o.y = m.y ? 0.0f : fmaf(v.y, sc, sh);
    o.z = m.z ? 0.0f : fmaf(v.z, sc, sh);
    o.w = m.w ? 0.0f : fmaf(v.w, sc, sh);
    reinterpret_cast<float4*>(out)[i4] = o;
}

// ---------------------------------------------------------------------------
// Host entry
// ---------------------------------------------------------------------------
extern "C" void kernel_launch(void* const* d_in, const int* in_sizes, int n_in,
                              void* d_out, int out_size)
{
    const float* prev    = (const float*)d_in[0];
    const float* curr    = (const float*)d_in[1];
    const void*  maskraw = d_in[2];

    // Resolve remaining params by element count (robust to scalar 'h' presence)
    const float *convw = 0, *convb = 0, *projw = 0, *gamma = 0, *beta = 0;
    for (int i = 3; i < n_in; i++) {
        const int s = in_sizes[i];
        if      (s == COUT * CIN * KS * KS) convw = (const float*)d_in[i];
        else if (s == NH * COUT)            projw = (const float*)d_in[i];
        else if (s == COUT)                 convb = (const float*)d_in[i];
        else if (s == NH) {
            if (!gamma) gamma = (const float*)d_in[i];
            else        beta  = (const float*)d_in[i];
        }
        // s == 1 -> scalar 'h' (hardcoded), ignored
    }

    cudaFuncSetAttribute(conv_kernel,
                         cudaFuncAttributeMaxDynamicSharedMemorySize, SMEM_BYTES);

    prep_kernel<<<1, 512>>>(maskraw);
    cumsum_kernel<<<(NB * CIN * LL) / 256, 256>>>(prev, curr);
    conv_kernel<<<NB * TT, 512, SMEM_BYTES>>>(convw, convb, projw);
    finalize_kernel<<<1, 32>>>(gamma, beta);
    bn_kernel<<<(NB * NH * TT * LL) / 4 / 256, 256>>>((float*)d_out);
}

// round 2
// speedup vs baseline: 1.1008x; 1.1008x over previous
#include <cuda_runtime.h>
#include <cstdint>

// Problem constants (fixed shapes for this problem instance)
#define NB   8      // batch
#define NH   8      // heads
#define TT   128    // time steps
#define HH   32     // height
#define WW   64     // width
#define LL   2048   // h*w
#define CIN  16     // 2*NH conv input channels
#define COUT 32     // conv output channels
#define KS   5      // conv kernel size
#define BN_EPS 1e-5f

typedef unsigned long long ull;

// Packed fp32x2 FMA (Blackwell sm_100a+): acc.lo += w.lo*x.lo; acc.hi += w.hi*x.hi
#define FMA2(acc, w, x) \
    asm("fma.rn.f32x2 %0, %1, %2, %0;" : "+l"(acc) : "l"(w), "l"(x))
#define PACK2(dst, f) \
    asm("mov.b64 %0, {%1, %1};" : "=l"(dst) : "r"(__float_as_uint(f)))

__device__ __forceinline__ float lo32(ull v) { return __uint_as_float((unsigned)v); }
__device__ __forceinline__ float hi32(ull v) { return __uint_as_float((unsigned)(v >> 32)); }

// ---------------------------------------------------------------------------
// Device scratch (allocation-free rule: __device__ globals)
// ---------------------------------------------------------------------------
__device__ float  g_acum[(size_t)NB * TT * CIN * LL];   // [(b*T+t)][ic][l]  exclusive cumsum
__device__ float  g_cov [(size_t)NB * NH * TT * LL];    // [b][n][t][l]  (== output layout)
__device__ int    g_mask[NB * LL];                      // canonical mask (1 = padded)
__device__ double g_sum[NH];
__device__ double g_ss [NH];
__device__ float  g_cnt;
__device__ float  g_scale[NH], g_shift[NH];

// ---------------------------------------------------------------------------
// Kernel 0: mask canonicalization + stat-accumulator reset (runs every launch)
// ---------------------------------------------------------------------------
__global__ void prep_kernel(const void* __restrict__ maskraw)
{
    __shared__ int s_hasF, s_hasP, s_cnt;
    const int tid = threadIdx.x;
    if (tid == 0) { s_hasF = 0; s_hasP = 0; s_cnt = 0; }
    __syncthreads();

    const unsigned* u32 = (const unsigned*)maskraw;
    int hf = 0, hp = 0;
    for (int i = tid; i < (NB * LL) / 4; i += blockDim.x) {
        unsigned v = u32[i];
        if (v == 0x3F800000u) hf = 1;      // float32 1.0 present -> float mask
        else if (v > 1u)      hp = 1;      // packed bool bytes (e.g. 0x0101)
    }
    if (hf) atomicOr(&s_hasF, 1);
    if (hp) atomicOr(&s_hasP, 1);
    __syncthreads();

    const int isBool = (!s_hasF) && s_hasP;
    const unsigned char* b8 = (const unsigned char*)maskraw;

    int localUnmasked = 0;
    for (int i = tid; i < NB * LL; i += blockDim.x) {
        int m = isBool ? (b8[i] != 0) : (u32[i] != 0u);
        g_mask[i] = m;
        localUnmasked += (m == 0);
    }
    atomicAdd(&s_cnt, localUnmasked);
    __syncthreads();

    if (tid == 0) {
        float cnt = (float)s_cnt * (float)TT;
        g_cnt = (cnt < 1.0f) ? 1.0f : cnt;
    }
    if (tid < NH) { g_sum[tid] = 0.0; g_ss[tid] = 0.0; }
}

// ---------------------------------------------------------------------------
// Kernel 1: exclusive cumsum over t, fused channel-concat [prev(8) | curr(8)]
// ---------------------------------------------------------------------------
__global__ void cumsum_kernel(const float* __restrict__ prev,
                              const float* __restrict__ curr)
{
    const int gid = blockIdx.x * blockDim.x + threadIdx.x;   // 262144
    const int b   = gid >> 15;
    const int rem = gid & 32767;
    const int cc  = rem >> 11;
    const int l   = rem & (LL - 1);

    const float* src = (cc < NH)
        ? prev + ((size_t)(b * NH + cc)       ) * TT * LL + l
        : curr + ((size_t)(b * NH + (cc - NH))) * TT * LL + l;

    size_t dst = ((size_t)(b * TT) * CIN + cc) * LL + l;

    float run = 0.0f;
    #pragma unroll 4
    for (int t = 0; t < TT; t++) {
        g_acum[dst] = run;
        run += src[(size_t)t * LL];
        dst += (size_t)CIN * LL;
    }
}

// ---------------------------------------------------------------------------
// Kernel 2: hot kernel. Per block = one (b,t) image:
//   5x5 conv (16->32) via packed f32x2 FMA + bias + ReLU + mask-zero
//   + 1x1 proj (32->8) + masked BN partials + cov store.
// ---------------------------------------------------------------------------
#define SIN_STRIDE 68                       // 64 + 2*2 halo
#define SIN_ROWS   36                       // 32 + 2*2 halo
#define SIN_PER_C  (SIN_ROWS * SIN_STRIDE)  // 2448
#define SIN_FLOATS (CIN * SIN_PER_C)        // 39168
#define SW_FLOATS  (COUT * CIN * KS * KS)   // 12800
#define SMEM_FLOATS (SIN_FLOATS + SW_FLOATS + 256 + 32 + 16)
#define SMEM_BYTES  (SMEM_FLOATS * 4)       // 209088

__global__ __launch_bounds__(512, 1)
void conv_kernel(const float* __restrict__ convw,
                 const float* __restrict__ convb,
                 const float* __restrict__ projw)
{
    extern __shared__ float sm[];
    float* s_in   = sm;                         // [ic][36][68], halo zero-padded
    float* s_w    = sm + SIN_FLOATS;            // [kidx(ic,ky,kx)][oc] (oc contiguous)
    float* s_proj = s_w + SW_FLOATS;            // [oc][n]
    float* s_cb   = s_proj + 256;               // [oc]
    float* s_blk  = s_cb + 32;                  // [sum(8) | sumsq(8)]

    const int tid = threadIdx.x;
    const int img = blockIdx.x;                 // = b*T + t
    const int b   = img >> 7;
    const int t   = img & (TT - 1);

    if (tid < 16)  s_blk[tid] = 0.0f;
    if (tid < 32)  s_cb[tid]  = convb[tid];
    if (tid < 256) {                            // s_proj[oc*8+n] = projw[n*32+oc]
        const int oc = tid >> 3, n = tid & 7;
        s_proj[tid] = projw[n * COUT + oc];
    }
    for (int i = tid; i < SW_FLOATS; i += 512) {
        const int oc = i & 31, kidx = i >> 5;
        s_w[i] = convw[oc * (CIN * KS * KS) + kidx];
    }
    for (int i = tid; i < SIN_FLOATS; i += 512) {
        const int ic  = i / SIN_PER_C;
        const int rem = i - ic * SIN_PER_C;
        const int R   = rem / SIN_STRIDE;
        const int C   = rem - R * SIN_STRIDE;
        const int rin = R - 2, cin = C - 2;
        float v = 0.0f;
        if ((unsigned)rin < (unsigned)HH && (unsigned)cin < (unsigned)WW)
            v = g_acum[((size_t)img * CIN + ic) * LL + rin * WW + cin];
        s_in[i] = v;
    }
    __syncthreads();

    const int warp = tid >> 5, lane = tid & 31;

    // 32 tasks: 16 row-pairs x 2 column halves; 16 warps x 2 iterations.
    for (int task = warp; task < 32; task += 16) {
        const int r0 = (task & 15) * 2;
        const int c  = ((task >> 4) << 5) + lane;

        // acc pairs: acc[j] covers oc {2j, 2j+1} (lo = even oc)
        ull acc0[16], acc1[16];
        #pragma unroll
        for (int j = 0; j < 16; j++) { acc0[j] = 0ull; acc1[j] = 0ull; }

        #pragma unroll 1
        for (int ic = 0; ic < CIN; ic++) {
            const float* sc_ = s_in + ic * SIN_PER_C;
            #pragma unroll 1
            for (int ky = 0; ky < KS; ky++) {
                const float* r0p = sc_ + (r0 + ky) * SIN_STRIDE + c;
                const float* r1p = r0p + SIN_STRIDE;
                const ulonglong2* wb = reinterpret_cast<const ulonglong2*>(
                                          s_w + (ic * 25 + ky * 5) * 32);
                #pragma unroll
                for (int kx = 0; kx < KS; kx++) {
                    const float i0 = r0p[kx];       // consecutive addrs: conflict-free
                    const float i1 = r1p[kx];
                    ull x0, x1;
                    PACK2(x0, i0);
                    PACK2(x1, i1);
                    const ulonglong2* w4 = wb + kx * 8;   // broadcast LDS.128
                    #pragma unroll
                    for (int u = 0; u < 8; u++) {
                        const ulonglong2 w = w4[u];       // 4 floats = 2 f32x2 pairs
                        FMA2(acc0[2*u    ], w.x, x0);
                        FMA2(acc0[2*u + 1], w.y, x0);
                        FMA2(acc1[2*u    ], w.x, x1);
                        FMA2(acc1[2*u + 1], w.y, x1);
                    }
                }
            }
        }

        // Epilogue: bias + ReLU + mask + 1x1 proj + store + BN partials
        float psum[NH], pss[NH];
        #pragma unroll
        for (int n = 0; n < NH; n++) { psum[n] = 0.0f; pss[n] = 0.0f; }

        #pragma unroll
        for (int r = 0; r < 2; r++) {
            const int row = r0 + r;
            const int hw  = row * WW + c;
            const int m   = g_mask[b * LL + hw];
            float p[NH];
            #pragma unroll
            for (int n = 0; n < NH; n++) p[n] = 0.0f;
            if (!m) {
                #pragma unroll
                for (int j = 0; j < 16; j++) {
                    const ull a = r ? acc1[j] : acc0[j];
                    float v0 = lo32(a) + s_cb[2*j];
                    float v1 = hi32(a) + s_cb[2*j + 1];
                    v0 = v0 > 0.0f ? v0 : 0.0f;
                    v1 = v1 > 0.0f ? v1 : 0.0f;
                    #pragma unroll
                    for (int n = 0; n < NH; n++)
                        p[n] += v0 * s_proj[(2*j) * NH + n]
                              + v1 * s_proj[(2*j + 1) * NH + n];
                }
            }
            #pragma unroll
            for (int n = 0; n < NH; n++) {
                g_cov[(((size_t)(b * NH + n)) * TT + t) * LL + hw] = p[n];
                if (!m) { psum[n] += p[n]; pss[n] += p[n] * p[n]; }
            }
        }

        // warp reduce -> block smem accumulators
        #pragma unroll
        for (int n = 0; n < NH; n++) {
            float s = psum[n], q = pss[n];
            #pragma unroll
            for (int off = 16; off > 0; off >>= 1) {
                s += __shfl_xor_sync(0xffffffffu, s, off);
                q += __shfl_xor_sync(0xffffffffu, q, off);
            }
            if (lane == 0) {
                atomicAdd(&s_blk[n],      s);
                atomicAdd(&s_blk[NH + n], q);
            }
        }
    }

    __syncthreads();
    if (tid < NH) {
        atomicAdd(&g_sum[tid], (double)s_blk[tid]);
        atomicAdd(&g_ss[tid],  (double)s_blk[NH + tid]);
    }
}

// ---------------------------------------------------------------------------
// Kernel 3: BN finalize (tiny)
// ---------------------------------------------------------------------------
__global__ void finalize_kernel(const float* __restrict__ gamma,
                                const float* __restrict__ beta)
{
    const int n = threadIdx.x;
    if (n < NH) {
        const double cnt  = (double)g_cnt;
        const double mean = g_sum[n] / cnt;
        double var  = g_ss[n] / cnt - mean * mean;
        if (var < 0.0) var = 0.0;
        const float inv = rsqrtf((float)var + BN_EPS);
        g_scale[n] = gamma[n] * inv;
        g_shift[n] = beta[n] - gamma[n] * inv * (float)mean;
    }
}

// ---------------------------------------------------------------------------
// Kernel 4: normalize + mask-zero, write to output
// ---------------------------------------------------------------------------
__global__ void bn_kernel(float* __restrict__ out)
{
    const size_t i4  = (size_t)blockIdx.x * blockDim.x + threadIdx.x;
    const size_t idx = i4 * 4;
    const int n  = (int)((idx >> 18) & 7);
    const int b  = (int)(idx >> 21);
    const int hw = (int)(idx & (LL - 1));

    const float4 v = *reinterpret_cast<const float4*>(&g_cov[idx]);
    const int4   m = *reinterpret_cast<const int4*>(&g_mask[b * LL + hw]);
    const float sc = g_scale[n], sh = g_shift[n];

    float4 o;
    o.x = m.x ? 0.0f : fmaf(v.x, sc, sh);
    o.y = m.y ? 0.0f : fmaf(v.y, sc, sh);
    o.z = m.z ? 0.0f : fmaf(v.z, sc, sh);
    o.w = m.w ? 0.0f : fmaf(v.w, sc, sh);
    reinterpret_cast<float4*>(out)[i4] = o;
}

// ---------------------------------------------------------------------------
// Host entry
// ---------------------------------------------------------------------------
extern "C" void kernel_launch(void* const* d_in, const int* in_sizes, int n_in,
                              void* d_out, int out_size)
{
    const float* prev    = (const float*)d_in[0];
    const float* curr    = (const float*)d_in[1];
    const void*  maskraw = d_in[2];

    const float *convw = 0, *convb = 0, *projw = 0, *gamma = 0, *beta = 0;
    for (int i = 3; i < n_in; i++) {
        const int s = in_sizes[i];
        if      (s == COUT * CIN * KS * KS) convw = (const float*)d_in[i];
        else if (s == NH * COUT)            projw = (const float*)d_in[i];
        else if (s == COUT)                 convb = (const float*)d_in[i];
        else if (s == NH) {
            if (!gamma) gamma = (const float*)d_in[i];
            else        beta  = (const float*)d_in[i];
        }
    }

    cudaFuncSetAttribute(conv_kernel,
                         cudaFuncAttributeMaxDynamicSharedMemorySize, SMEM_BYTES);

    prep_kernel<<<1, 512>>>(maskraw);
    cumsum_kernel<<<(NB * CIN * LL) / 256, 256>>>(prev, curr);
    conv_kernel<<<NB * TT, 512, SMEM_BYTES>>>(convw, convb, projw);
    finalize_kernel<<<1, 32>>>(gamma, beta);
    bn_kernel<<<(NB * NH * TT * LL) / 4 / 256, 256>>>((float*)d_out);
}

// round 5
// speedup vs baseline: 1.1864x; 1.0778x over previous
#include <cuda_runtime.h>
#include <cstdint>

#define NB   8
#define NH   8
#define TT   128
#define HH   32
#define WW   64
#define LL   2048
#define CIN  16
#define COUT 32
#define KS   5
#define BN_EPS 1e-5f

typedef unsigned long long ull;

// Packed fp32x2 FMA (Blackwell): acc.lo += w.lo*x.lo; acc.hi += w.hi*x.hi
#define FMA2(acc, w, x) \
    asm("fma.rn.f32x2 %0, %1, %2, %0;" : "+l"(acc) : "l"(w), "l"(x))
#define PACK2(dst, f) \
    asm("mov.b64 %0, {%1, %1};" : "=l"(dst) : "r"(__float_as_uint(f)))

__device__ __forceinline__ float lo32(ull v) { return __uint_as_float((unsigned)v); }
__device__ __forceinline__ float hi32(ull v) { return __uint_as_float((unsigned)(v >> 32)); }

__device__ __forceinline__ void cpasync8(float* dst, const float* src) {
    unsigned d = (unsigned)__cvta_generic_to_shared(dst);
    asm volatile("cp.async.ca.shared.global [%0], [%1], 8;" :: "r"(d), "l"(src));
}
#define CP_COMMIT() asm volatile("cp.async.commit_group;")
#define CP_WAIT0()  asm volatile("cp.async.wait_group 0;")

// ---------------------------------------------------------------------------
// Device scratch
// ---------------------------------------------------------------------------
__device__ __align__(16) float g_acum[(size_t)NB * TT * CIN * LL]; // [(b*T+t)][ic][l]
__device__ __align__(16) float g_cov [(size_t)NB * NH * TT * LL];  // output layout
__device__ int    g_mask[NB * LL];
__device__ double g_sum[NH];
__device__ double g_ss [NH];
__device__ float  g_cnt;
__device__ float  g_scale[NH], g_shift[NH];

// ---------------------------------------------------------------------------
// Kernel 0: mask canonicalization + stat reset
// ---------------------------------------------------------------------------
__global__ void prep_kernel(const void* __restrict__ maskraw)
{
    __shared__ int s_hasF, s_hasP, s_cnt;
    const int tid = threadIdx.x;
    if (tid == 0) { s_hasF = 0; s_hasP = 0; s_cnt = 0; }
    __syncthreads();

    const unsigned* u32 = (const unsigned*)maskraw;
    int hf = 0, hp = 0;
    for (int i = tid; i < (NB * LL) / 4; i += blockDim.x) {
        unsigned v = u32[i];
        if (v == 0x3F800000u) hf = 1;
        else if (v > 1u)      hp = 1;
    }
    if (hf) atomicOr(&s_hasF, 1);
    if (hp) atomicOr(&s_hasP, 1);
    __syncthreads();

    const int isBool = (!s_hasF) && s_hasP;
    const unsigned char* b8 = (const unsigned char*)maskraw;

    int localUnmasked = 0;
    for (int i = tid; i < NB * LL; i += blockDim.x) {
        int m = isBool ? (b8[i] != 0) : (u32[i] != 0u);
        g_mask[i] = m;
        localUnmasked += (m == 0);
    }
    atomicAdd(&s_cnt, localUnmasked);
    __syncthreads();

    if (tid == 0) {
        float cnt = (float)s_cnt * (float)TT;
        g_cnt = (cnt < 1.0f) ? 1.0f : cnt;
    }
    if (tid < NH) { g_sum[tid] = 0.0; g_ss[tid] = 0.0; }
}

// ---------------------------------------------------------------------------
// Kernel 1: exclusive cumsum over t (float4 vectorized)
// ---------------------------------------------------------------------------
__global__ void cumsum_kernel(const float* __restrict__ prev,
                              const float* __restrict__ curr)
{
    const int gid = blockIdx.x * blockDim.x + threadIdx.x;  // 65536
    const int b   = gid >> 13;
    const int cc  = (gid >> 9) & 15;
    const int l4  = gid & 511;

    const float4* src = (const float4*)((cc < NH)
        ? prev + ((size_t)(b * NH + cc)       ) * TT * LL
        : curr + ((size_t)(b * NH + (cc - NH))) * TT * LL) + l4;

    float4* dst = (float4*)(g_acum + ((size_t)(b * TT) * CIN + cc) * LL) + l4;

    float4 run = make_float4(0.f, 0.f, 0.f, 0.f);
    #pragma unroll 4
    for (int t = 0; t < TT; t++) {
        *dst = run;
        const float4 v = src[(size_t)t * (LL / 4)];
        run.x += v.x; run.y += v.y; run.z += v.z; run.w += v.w;
        dst += (size_t)CIN * (LL / 4);
    }
}

// ---------------------------------------------------------------------------
// Kernel 2: per-image conv block (known-good R2 structure)
//   5x5 conv (16->32) via FFMA2 + bias + ReLU + mask + 1x1 proj + BN partials
// ---------------------------------------------------------------------------
#define SIN_STRIDE 68                       // 64 + 2*2 halo
#define SIN_ROWS   36                       // 32 + 2*2 halo
#define SIN_PER_C  (SIN_ROWS * SIN_STRIDE)  // 2448
#define SIN_FLOATS (CIN * SIN_PER_C)        // 39168
#define SW_FLOATS  (COUT * CIN * KS * KS)   // 12800
#define SMEM_FLOATS (SIN_FLOATS + SW_FLOATS + 256 + 32 + 16)
#define SMEM_BYTES  (SMEM_FLOATS * 4)       // 209088

__global__ __launch_bounds__(512, 1)
void conv_kernel(const float* __restrict__ convw,
                 const float* __restrict__ convb,
                 const float* __restrict__ projw)
{
    extern __shared__ float sm[];
    float* s_in   = sm;                         // [ic][36][68], halo zero
    float* s_w    = sm + SIN_FLOATS;            // [kidx][oc]
    float* s_proj = s_w + SW_FLOATS;            // [oc][n]
    float* s_cb   = s_proj + 256;
    float* s_blk  = s_cb + 32;                  // [sum(8)|sumsq(8)]

    const int tid = threadIdx.x;
    const int img = blockIdx.x;                 // b*T + t
    const int b   = img >> 7;
    const int t   = img & (TT - 1);

    // Zero the whole input tile (halo included) + small tables
    for (int j = tid; j < SIN_FLOATS / 4; j += 512)
        reinterpret_cast<float4*>(s_in)[j] = make_float4(0.f, 0.f, 0.f, 0.f);
    if (tid < 16)  s_blk[tid] = 0.0f;
    if (tid < 32)  s_cb[tid]  = convb[tid];
    if (tid < 256) {
        const int oc = tid >> 3, n = tid & 7;
        s_proj[tid] = projw[n * COUT + oc];
    }
    for (int i = tid; i < SW_FLOATS; i += 512) {
        const int oc = i & 31, kidx = i >> 5;
        s_w[i] = convw[oc * (CIN * KS * KS) + kidx];
    }
    __syncthreads();   // zeroing done before async writes to the same region

    // cp.async the 16ch x 32row x 64col interior (8B chunks, high MLP)
    const float* src0 = g_acum + (size_t)img * CIN * LL;
    for (int j = tid; j < 16384; j += 512) {
        const int c2 = j & 31;         // 8B chunk within row
        const int r  = (j >> 5) & 31;  // image row
        const int ic = j >> 10;        // channel
        cpasync8(s_in + ic * SIN_PER_C + (r + 2) * SIN_STRIDE + 2 + c2 * 2,
                 src0 + (size_t)ic * LL + r * WW + c2 * 2);
    }
    CP_COMMIT();
    CP_WAIT0();
    __syncthreads();

    const int warp = tid >> 5, lane = tid & 31;

    // 32 tasks: 16 row-pairs x 2 column halves; 16 warps x 2 iterations.
    for (int task = warp; task < 32; task += 16) {
        const int r0 = (task & 15) * 2;
        const int c  = ((task >> 4) << 5) + lane;

        ull acc0[16], acc1[16];
        #pragma unroll
        for (int j = 0; j < 16; j++) { acc0[j] = 0ull; acc1[j] = 0ull; }

        #pragma unroll 1
        for (int ic = 0; ic < CIN; ic++) {
            const float* sc_ = s_in + ic * SIN_PER_C + r0 * SIN_STRIDE + c;
            const ulonglong2* wic = reinterpret_cast<const ulonglong2*>(
                                        s_w + ic * 25 * 32);
            #pragma unroll
            for (int ky = 0; ky < KS; ky++) {
                const float* r0p = sc_ + ky * SIN_STRIDE;
                const float* r1p = r0p + SIN_STRIDE;
                const ulonglong2* wb = wic + ky * 5 * 8;
                #pragma unroll
                for (int kx = 0; kx < KS; kx++) {
                    const float i0 = r0p[kx];       // consecutive: conflict-free
                    const float i1 = r1p[kx];
                    ull x0, x1;
                    PACK2(x0, i0);
                    PACK2(x1, i1);
                    const ulonglong2* w4 = wb + kx * 8;   // broadcast LDS.128
                    #pragma unroll
                    for (int u = 0; u < 8; u++) {
                        const ulonglong2 w = w4[u];
                        FMA2(acc0[2*u    ], w.x, x0);
                        FMA2(acc0[2*u + 1], w.y, x0);
                        FMA2(acc1[2*u    ], w.x, x1);
                        FMA2(acc1[2*u + 1], w.y, x1);
                    }
                }
            }
        }

        // Epilogue: bias + ReLU + mask + 1x1 proj + store + BN partials
        float psum[NH], pss[NH];
        #pragma unroll
        for (int n = 0; n < NH; n++) { psum[n] = 0.0f; pss[n] = 0.0f; }

        #pragma unroll
        for (int r = 0; r < 2; r++) {
            const int row = r0 + r;
            const int hw  = row * WW + c;
            const int m   = g_mask[b * LL + hw];
            float p[NH];
            #pragma unroll
            for (int n = 0; n < NH; n++) p[n] = 0.0f;
            if (!m) {
                #pragma unroll
                for (int j = 0; j < 16; j++) {
                    const ull a = r ? acc1[j] : acc0[j];
                    float v0 = lo32(a) + s_cb[2*j];
                    float v1 = hi32(a) + s_cb[2*j + 1];
                    v0 = v0 > 0.0f ? v0 : 0.0f;
                    v1 = v1 > 0.0f ? v1 : 0.0f;
                    #pragma unroll
                    for (int n = 0; n < NH; n++)
                        p[n] += v0 * s_proj[(2*j) * NH + n]
                              + v1 * s_proj[(2*j + 1) * NH + n];
                }
            }
            #pragma unroll
            for (int n = 0; n < NH; n++) {
                g_cov[(((size_t)(b * NH + n)) * TT + t) * LL + hw] = p[n];
                if (!m) { psum[n] += p[n]; pss[n] += p[n] * p[n]; }
            }
        }

        // warp reduce -> block smem accumulators
        #pragma unroll
        for (int n = 0; n < NH; n++) {
            float s = psum[n], q = pss[n];
            #pragma unroll
            for (int off = 16; off > 0; off >>= 1) {
                s += __shfl_xor_sync(0xffffffffu, s, off);
                q += __shfl_xor_sync(0xffffffffu, q, off);
            }
            if (lane == 0) {
                atomicAdd(&s_blk[n],      s);
                atomicAdd(&s_blk[NH + n], q);
            }
        }
    }

    __syncthreads();
    if (tid < NH) {
        atomicAdd(&g_sum[tid], (double)s_blk[tid]);
        atomicAdd(&g_ss[tid],  (double)s_blk[NH + tid]);
    }
}

// ---------------------------------------------------------------------------
// Kernel 3: BN finalize
// ---------------------------------------------------------------------------
__global__ void finalize_kernel(const float* __restrict__ gamma,
                                const float* __restrict__ beta)
{
    const int n = threadIdx.x;
    if (n < NH) {
        const double cnt  = (double)g_cnt;
        const double mean = g_sum[n] / cnt;
        double var  = g_ss[n] / cnt - mean * mean;
        if (var < 0.0) var = 0.0;
        const float inv = rsqrtf((float)var + BN_EPS);
        g_scale[n] = gamma[n] * inv;
        g_shift[n] = beta[n] - gamma[n] * inv * (float)mean;
    }
}

// ---------------------------------------------------------------------------
// Kernel 4: normalize + mask-zero -> output
// ---------------------------------------------------------------------------
__global__ void bn_kernel(float* __restrict__ out)
{
    const size_t i4  = (size_t)blockIdx.x * blockDim.x + threadIdx.x;
    const size_t idx = i4 * 4;
    const int n  = (int)((idx >> 18) & 7);
    const int b  = (int)(idx >> 21);
    const int hw = (int)(idx & (LL - 1));

    const float4 v = *reinterpret_cast<const float4*>(&g_cov[idx]);
    const int4   m = *reinterpret_cast<const int4*>(&g_mask[b * LL + hw]);
    const float sc = g_scale[n], sh = g_shift[n];

    float4 o;
    o.x = m.x ? 0.0f : fmaf(v.x, sc, sh);
    o.y = m.y ? 0.0f : fmaf(v.y, sc, sh);
    o.z = m.z ? 0.0f : fmaf(v.z, sc, sh);
    o.w = m.w ? 0.0f : fmaf(v.w, sc, sh);
    reinterpret_cast<float4*>(out)[i4] = o;
}

// ---------------------------------------------------------------------------
// Host entry
// ---------------------------------------------------------------------------
extern "C" void kernel_launch(void* const* d_in, const int* in_sizes, int n_in,
                              void* d_out, int out_size)
{
    const float* prev    = (const float*)d_in[0];
    const float* curr    = (const float*)d_in[1];
    const void*  maskraw = d_in[2];

    const float *convw = 0, *convb = 0, *projw = 0, *gamma = 0, *beta = 0;
    for (int i = 3; i < n_in; i++) {
        const int s = in_sizes[i];
        if      (s == COUT * CIN * KS * KS) convw = (const float*)d_in[i];
        else if (s == NH * COUT)            projw = (const float*)d_in[i];
        else if (s == COUT)                 convb = (const float*)d_in[i];
        else if (s == NH) {
            if (!gamma) gamma = (const float*)d_in[i];
            else        beta  = (const float*)d_in[i];
        }
    }

    cudaFuncSetAttribute(conv_kernel,
                         cudaFuncAttributeMaxDynamicSharedMemorySize, SMEM_BYTES);

    prep_kernel<<<1, 512>>>(maskraw);
    cumsum_kernel<<<(NB * CIN * LL / 4) / 256, 256>>>(prev, curr);
    conv_kernel<<<NB * TT, 512, SMEM_BYTES>>>(convw, convb, projw);
    finalize_kernel<<<1, 32>>>(gamma, beta);
    bn_kernel<<<(NB * NH * TT * LL) / 4 / 256, 256>>>((float*)d_out);
}

// round 6
// speedup vs baseline: 1.1922x; 1.0048x over previous
#include <cuda_runtime.h>
#include <cstdint>

#define NB   8
#define NH   8
#define TT   128
#define HH   32
#define WW   64
#define LL   2048
#define CIN  16
#define COUT 32
#define KS   5
#define BN_EPS 1e-5f

typedef unsigned long long ull;

// Packed fp32x2 FMA (Blackwell): acc.lo += w.lo*x.lo; acc.hi += w.hi*x.hi
#define FMA2(acc, w, x) \
    asm("fma.rn.f32x2 %0, %1, %2, %0;" : "+l"(acc) : "l"(w), "l"(x))
#define PACK2(dst, f) \
    asm("mov.b64 %0, {%1, %1};" : "=l"(dst) : "r"(__float_as_uint(f)))

__device__ __forceinline__ float lo32(ull v) { return __uint_as_float((unsigned)v); }
__device__ __forceinline__ float hi32(ull v) { return __uint_as_float((unsigned)(v >> 32)); }

__device__ __forceinline__ void cpasync8(float* dst, const float* src) {
    unsigned d = (unsigned)__cvta_generic_to_shared(dst);
    asm volatile("cp.async.ca.shared.global [%0], [%1], 8;" :: "r"(d), "l"(src));
}
#define CP_COMMIT() asm volatile("cp.async.commit_group;")
#define CP_WAIT0()  asm volatile("cp.async.wait_group 0;")

// ---------------------------------------------------------------------------
// Device scratch
// ---------------------------------------------------------------------------
__device__ __align__(16) float g_acum[(size_t)NB * TT * CIN * LL]; // [(b*T+t)][ic][l]
__device__ __align__(16) float g_cov [(size_t)NB * NH * TT * LL];  // output layout
__device__ int    g_mask[NB * LL];
__device__ double g_sum[NH];
__device__ double g_ss [NH];
__device__ float  g_cnt;
__device__ float  g_scale[NH], g_shift[NH];

// ---------------------------------------------------------------------------
// Kernel 0: mask canonicalization + stat reset
// ---------------------------------------------------------------------------
__global__ void prep_kernel(const void* __restrict__ maskraw)
{
    __shared__ int s_hasF, s_hasP, s_cnt;
    const int tid = threadIdx.x;
    if (tid == 0) { s_hasF = 0; s_hasP = 0; s_cnt = 0; }
    __syncthreads();

    const unsigned* u32 = (const unsigned*)maskraw;
    int hf = 0, hp = 0;
    for (int i = tid; i < (NB * LL) / 4; i += blockDim.x) {
        unsigned v = u32[i];
        if (v == 0x3F800000u) hf = 1;
        else if (v > 1u)      hp = 1;
    }
    if (hf) atomicOr(&s_hasF, 1);
    if (hp) atomicOr(&s_hasP, 1);
    __syncthreads();

    const int isBool = (!s_hasF) && s_hasP;
    const unsigned char* b8 = (const unsigned char*)maskraw;

    int localUnmasked = 0;
    for (int i = tid; i < NB * LL; i += blockDim.x) {
        int m = isBool ? (b8[i] != 0) : (u32[i] != 0u);
        g_mask[i] = m;
        localUnmasked += (m == 0);
    }
    atomicAdd(&s_cnt, localUnmasked);
    __syncthreads();

    if (tid == 0) {
        float cnt = (float)s_cnt * (float)TT;
        g_cnt = (cnt < 1.0f) ? 1.0f : cnt;
    }
    if (tid < NH) { g_sum[tid] = 0.0; g_ss[tid] = 0.0; }
}

// ---------------------------------------------------------------------------
// Kernel 1: exclusive cumsum over t (float4 vectorized)
// ---------------------------------------------------------------------------
__global__ void cumsum_kernel(const float* __restrict__ prev,
                              const float* __restrict__ curr)
{
    const int gid = blockIdx.x * blockDim.x + threadIdx.x;  // 65536
    const int b   = gid >> 13;
    const int cc  = (gid >> 9) & 15;
    const int l4  = gid & 511;

    const float4* src = (const float4*)((cc < NH)
        ? prev + ((size_t)(b * NH + cc)       ) * TT * LL
        : curr + ((size_t)(b * NH + (cc - NH))) * TT * LL) + l4;

    float4* dst = (float4*)(g_acum + ((size_t)(b * TT) * CIN + cc) * LL) + l4;

    float4 run = make_float4(0.f, 0.f, 0.f, 0.f);
    #pragma unroll 4
    for (int t = 0; t < TT; t++) {
        *dst = run;
        const float4 v = src[(size_t)t * (LL / 4)];
        run.x += v.x; run.y += v.y; run.z += v.z; run.w += v.w;
        dst += (size_t)CIN * (LL / 4);
    }
}

// ---------------------------------------------------------------------------
// Kernel 2: per-image conv block (known-good R2 structure)
//   5x5 conv (16->32) via FFMA2 + bias + ReLU + mask + 1x1 proj + BN partials
// ---------------------------------------------------------------------------
#define SIN_STRIDE 68                       // 64 + 2*2 halo
#define SIN_ROWS   36                       // 32 + 2*2 halo
#define SIN_PER_C  (SIN_ROWS * SIN_STRIDE)  // 2448
#define SIN_FLOATS (CIN * SIN_PER_C)        // 39168
#define SW_FLOATS  (COUT * CIN * KS * KS)   // 12800
#define SMEM_FLOATS (SIN_FLOATS + SW_FLOATS + 256 + 32 + 16)
#define SMEM_BYTES  (SMEM_FLOATS * 4)       // 209088

__global__ __launch_bounds__(512, 1)
void conv_kernel(const float* __restrict__ convw,
                 const float* __restrict__ convb,
                 const float* __restrict__ projw)
{
    extern __shared__ float sm[];
    float* s_in   = sm;                         // [ic][36][68], halo zero
    float* s_w    = sm + SIN_FLOATS;            // [kidx][oc]
    float* s_proj = s_w + SW_FLOATS;            // [oc][n]
    float* s_cb   = s_proj + 256;
    float* s_blk  = s_cb + 32;                  // [sum(8)|sumsq(8)]

    const int tid = threadIdx.x;
    const int img = blockIdx.x;                 // b*T + t
    const int b   = img >> 7;
    const int t   = img & (TT - 1);

    // Zero the whole input tile (halo included) + small tables
    for (int j = tid; j < SIN_FLOATS / 4; j += 512)
        reinterpret_cast<float4*>(s_in)[j] = make_float4(0.f, 0.f, 0.f, 0.f);
    if (tid < 16)  s_blk[tid] = 0.0f;
    if (tid < 32)  s_cb[tid]  = convb[tid];
    if (tid < 256) {
        const int oc = tid >> 3, n = tid & 7;
        s_proj[tid] = projw[n * COUT + oc];
    }
    for (int i = tid; i < SW_FLOATS; i += 512) {
        const int oc = i & 31, kidx = i >> 5;
        s_w[i] = convw[oc * (CIN * KS * KS) + kidx];
    }
    __syncthreads();   // zeroing done before async writes to the same region

    // cp.async the 16ch x 32row x 64col interior (8B chunks, high MLP)
    const float* src0 = g_acum + (size_t)img * CIN * LL;
    for (int j = tid; j < 16384; j += 512) {
        const int c2 = j & 31;         // 8B chunk within row
        const int r  = (j >> 5) & 31;  // image row
        const int ic = j >> 10;        // channel
        cpasync8(s_in + ic * SIN_PER_C + (r + 2) * SIN_STRIDE + 2 + c2 * 2,
                 src0 + (size_t)ic * LL + r * WW + c2 * 2);
    }
    CP_COMMIT();
    CP_WAIT0();
    __syncthreads();

    const int warp = tid >> 5, lane = tid & 31;

    // 32 tasks: 16 row-pairs x 2 column halves; 16 warps x 2 iterations.
    for (int task = warp; task < 32; task += 16) {
        const int r0 = (task & 15) * 2;
        const int c  = ((task >> 4) << 5) + lane;

        ull acc0[16], acc1[16];
        #pragma unroll
        for (int j = 0; j < 16; j++) { acc0[j] = 0ull; acc1[j] = 0ull; }

        #pragma unroll 1
        for (int ic = 0; ic < CIN; ic++) {
            const float* sc_ = s_in + ic * SIN_PER_C + r0 * SIN_STRIDE + c;
            const ulonglong2* wic = reinterpret_cast<const ulonglong2*>(
                                        s_w + ic * 25 * 32);
            #pragma unroll
            for (int ky = 0; ky < KS; ky++) {
                const float* r0p = sc_ + ky * SIN_STRIDE;
                const float* r1p = r0p + SIN_STRIDE;
                const ulonglong2* wb = wic + ky * 5 * 8;
                #pragma unroll
                for (int kx = 0; kx < KS; kx++) {
                    const float i0 = r0p[kx];       // consecutive: conflict-free
                    const float i1 = r1p[kx];
                    ull x0, x1;
                    PACK2(x0, i0);
                    PACK2(x1, i1);
                    const ulonglong2* w4 = wb + kx * 8;   // broadcast LDS.128
                    #pragma unroll
                    for (int u = 0; u < 8; u++) {
                        const ulonglong2 w = w4[u];
                        FMA2(acc0[2*u    ], w.x, x0);
                        FMA2(acc0[2*u + 1], w.y, x0);
                        FMA2(acc1[2*u    ], w.x, x1);
                        FMA2(acc1[2*u + 1], w.y, x1);
                    }
                }
            }
        }

        // Epilogue: bias + ReLU + mask + 1x1 proj + store + BN partials
        float psum[NH], pss[NH];
        #pragma unroll
        for (int n = 0; n < NH; n++) { psum[n] = 0.0f; pss[n] = 0.0f; }

        #pragma unroll
        for (int r = 0; r < 2; r++) {
            const int row = r0 + r;
            const int hw  = row * WW + c;
            const int m   = g_mask[b * LL + hw];
            float p[NH];
            #pragma unroll
            for (int n = 0; n < NH; n++) p[n] = 0.0f;
            if (!m) {
                #pragma unroll
                for (int j = 0; j < 16; j++) {
                    const ull a = r ? acc1[j] : acc0[j];
                    float v0 = lo32(a) + s_cb[2*j];
                    float v1 = hi32(a) + s_cb[2*j + 1];
                    v0 = v0 > 0.0f ? v0 : 0.0f;
                    v1 = v1 > 0.0f ? v1 : 0.0f;
                    #pragma unroll
                    for (int n = 0; n < NH; n++)
                        p[n] += v0 * s_proj[(2*j) * NH + n]
                              + v1 * s_proj[(2*j + 1) * NH + n];
                }
            }
            #pragma unroll
            for (int n = 0; n < NH; n++) {
                g_cov[(((size_t)(b * NH + n)) * TT + t) * LL + hw] = p[n];
                if (!m) { psum[n] += p[n]; pss[n] += p[n] * p[n]; }
            }
        }

        // warp reduce -> block smem accumulators
        #pragma unroll
        for (int n = 0; n < NH; n++) {
            float s = psum[n], q = pss[n];
            #pragma unroll
            for (int off = 16; off > 0; off >>= 1) {
                s += __shfl_xor_sync(0xffffffffu, s, off);
                q += __shfl_xor_sync(0xffffffffu, q, off);
            }
            if (lane == 0) {
                atomicAdd(&s_blk[n],      s);
                atomicAdd(&s_blk[NH + n], q);
            }
        }
    }

    __syncthreads();
    if (tid < NH) {
        atomicAdd(&g_sum[tid], (double)s_blk[tid]);
        atomicAdd(&g_ss[tid],  (double)s_blk[NH + tid]);
    }
}

// ---------------------------------------------------------------------------
// Kernel 3: BN finalize
// ---------------------------------------------------------------------------
__global__ void finalize_kernel(const float* __restrict__ gamma,
                                const float* __restrict__ beta)
{
    const int n = threadIdx.x;
    if (n < NH) {
        const double cnt  = (double)g_cnt;
        const double mean = g_sum[n] / cnt;
        double var  = g_ss[n] / cnt - mean * mean;
        if (var < 0.0) var = 0.0;
        const float inv = rsqrtf((float)var + BN_EPS);
        g_scale[n] = gamma[n] * inv;
        g_shift[n] = beta[n] - gamma[n] * inv * (float)mean;
    }
}

// ---------------------------------------------------------------------------
// Kernel 4: normalize + mask-zero -> output
// ---------------------------------------------------------------------------
__global__ void bn_kernel(float* __restrict__ out)
{
    const size_t i4  = (size_t)blockIdx.x * blockDim.x + threadIdx.x;
    const size_t idx = i4 * 4;
    const int n  = (int)((idx >> 18) & 7);
    const int b  = (int)(idx >> 21);
    const int hw = (int)(idx & (LL - 1));

    const float4 v = *reinterpret_cast<const float4*>(&g_cov[idx]);
    const int4   m = *reinterpret_cast<const int4*>(&g_mask[b * LL + hw]);
    const float sc = g_scale[n], sh = g_shift[n];

    float4 o;
    o.x = m.x ? 0.0f : fmaf(v.x, sc, sh);
    o.y = m.y ? 0.0f : fmaf(v.y, sc, sh);
    o.z = m.z ? 0.0f : fmaf(v.z, sc, sh);
    o.w = m.w ? 0.0f : fmaf(v.w, sc, sh);
    reinterpret_cast<float4*>(out)[i4] = o;
}

// ---------------------------------------------------------------------------
// Host entry
// ---------------------------------------------------------------------------
extern "C" void kernel_launch(void* const* d_in, const int* in_sizes, int n_in,
                              void* d_out, int out_size)
{
    const float* prev    = (const float*)d_in[0];
    const float* curr    = (const float*)d_in[1];
    const void*  maskraw = d_in[2];

    const float *convw = 0, *convb = 0, *projw = 0, *gamma = 0, *beta = 0;
    for (int i = 3; i < n_in; i++) {
        const int s = in_sizes[i];
        if      (s == COUT * CIN * KS * KS) convw = (const float*)d_in[i];
        else if (s == NH * COUT)            projw = (const float*)d_in[i];
        else if (s == COUT)                 convb = (const float*)d_in[i];
        else if (s == NH) {
            if (!gamma) gamma = (const float*)d_in[i];
            else        beta  = (const float*)d_in[i];
        }
    }

    cudaFuncSetAttribute(conv_kernel,
                         cudaFuncAttributeMaxDynamicSharedMemorySize, SMEM_BYTES);

    prep_kernel<<<1, 512>>>(maskraw);
    cumsum_kernel<<<(NB * CIN * LL / 4) / 256, 256>>>(prev, curr);
    conv_kernel<<<NB * TT, 512, SMEM_BYTES>>>(convw, convb, projw);
    finalize_kernel<<<1, 32>>>(gamma, beta);
    bn_kernel<<<(NB * NH * TT * LL) / 4 / 256, 256>>>((float*)d_out);
}